// round 6
// baseline (speedup 1.0000x reference)
#include <cuda_runtime.h>

// Problem constants
#define BB 128
#define JJ 17
#define YY 96
#define XX 72
#define YX (YY * XX)                 // 6912
#define NTOT (BB * JJ * YX)          // 15,040,512 elements per plane
#define N4 (NTOT / 4)                // 3,760,128 float4 chunks per plane

#define NBLK 1184                    // 148 SMs * 8 blocks (2048 thr/SM, one wave)
#define NTHR 256

static __device__ double g_partials[NBLK];
static __device__ unsigned int g_count = 0;   // auto-wraps back to 0 each launch

__global__ void __launch_bounds__(NTHR) regloss_fused(
    const float* __restrict__ loc,
    const float* __restrict__ cord,
    const float* __restrict__ tw,
    float* __restrict__ out)
{
    const float4* __restrict__ loc0 = reinterpret_cast<const float4*>(loc);
    const float4* __restrict__ loc1 = reinterpret_cast<const float4*>(loc + NTOT);

    float acc = 0.0f;
    const int stride = gridDim.x * blockDim.x;
    for (int i = blockIdx.x * blockDim.x + threadIdx.x; i < N4; i += stride) {
        const int n  = i * 4;
        const int m  = n / YX;            // = b*J + j (same flat index for tw AND cord)
        const int p  = n - m * YX;
        const int y  = p / XX;
        const int x0 = p - y * XX;

        const float w  = __ldg(tw + m);
        const float cx = __ldg(cord + m);            // cord[0] flat index == m
        const float cy = __ldg(cord + JJ * BB + m);  // cord[1]

        const float4 lx = __ldg(loc0 + i);
        const float4 ly = __ldg(loc1 + i);

        // int32-truncated ground-truth shifts (toward zero, matches astype(int32))
        const float gy  = truncf((float)y - cy);
        const float gx0 = truncf((float)(x0 + 0) - cx);
        const float gx1 = truncf((float)(x0 + 1) - cx);
        const float gx2 = truncf((float)(x0 + 2) - cx);
        const float gx3 = truncf((float)(x0 + 3) - cx);

        float d;
        d = (lx.x - gx0) * w; acc = fmaf(d, d, acc);
        d = (lx.y - gx1) * w; acc = fmaf(d, d, acc);
        d = (lx.z - gx2) * w; acc = fmaf(d, d, acc);
        d = (lx.w - gx3) * w; acc = fmaf(d, d, acc);
        d = (ly.x - gy)  * w; acc = fmaf(d, d, acc);
        d = (ly.y - gy)  * w; acc = fmaf(d, d, acc);
        d = (ly.z - gy)  * w; acc = fmaf(d, d, acc);
        d = (ly.w - gy)  * w; acc = fmaf(d, d, acc);
    }

    // ── Block tree reduction (deterministic) ──
    __shared__ float sm[NTHR];
    __shared__ bool is_last;
    sm[threadIdx.x] = acc;
    __syncthreads();
    #pragma unroll
    for (int s = NTHR / 2; s >= 32; s >>= 1) {
        if (threadIdx.x < s) sm[threadIdx.x] += sm[threadIdx.x + s];
        __syncthreads();
    }
    if (threadIdx.x < 32) {
        float v = sm[threadIdx.x];
        #pragma unroll
        for (int off = 16; off > 0; off >>= 1)
            v += __shfl_down_sync(0xFFFFFFFFu, v, off);
        if (threadIdx.x == 0) {
            g_partials[blockIdx.x] = (double)v;
            __threadfence();
            // atomicInc wraps NBLK-1 -> 0, so the counter self-resets for the
            // next graph replay. Old value == NBLK-1 identifies the last block.
            unsigned int old = atomicInc(&g_count, NBLK - 1);
            is_last = (old == NBLK - 1);
        }
    }
    __syncthreads();

    // ── Last block to arrive performs the final (deterministic) reduction ──
    if (is_last) {
        __shared__ double smd[NTHR];
        double s = 0.0;
        for (int i = threadIdx.x; i < NBLK; i += NTHR)
            s += __ldcg(&g_partials[i]);    // L2 read, skip (possibly stale) L1
        smd[threadIdx.x] = s;
        __syncthreads();
        #pragma unroll
        for (int st = NTHR / 2; st > 0; st >>= 1) {
            if (threadIdx.x < st) smd[threadIdx.x] += smd[threadIdx.x + st];
            __syncthreads();
        }
        if (threadIdx.x == 0) {
            // loss = 0.5 * Sigma / (B*YX) / J
            const double scale = 0.5 / (double)NTOT;
            out[0] = (float)(smd[0] * scale);
        }
    }
}

extern "C" void kernel_launch(void* const* d_in, const int* in_sizes, int n_in,
                              void* d_out, int out_size)
{
    const float* loc  = (const float*)d_in[0];   // (2, B, J, Y, X) fp32
    const float* cord = (const float*)d_in[1];   // (2, J, B) fp32
    const float* tw   = (const float*)d_in[2];   // (B, J, 1) fp32
    float* out = (float*)d_out;

    regloss_fused<<<NBLK, NTHR>>>(loc, cord, tw, out);
}

// round 7
// speedup vs baseline: 1.0334x; 1.0334x over previous
#include <cuda_runtime.h>

// Problem constants
#define BB 128
#define JJ 17
#define YY 96
#define XX 72
#define YX (YY * XX)                 // 6912
#define NTOT (BB * JJ * YX)          // 15,040,512 elements per plane
#define N4 (NTOT / 4)                // 3,760,128 float4 chunks per plane

#define NBLK 1184                    // 148 SMs * 8 blocks (2048 thr/SM, one wave)
#define NTHR 256

static __device__ double g_partials[NBLK];

// ── Primary: byte-identical to the proven 18.6us R4 streaming kernel ──
__global__ void __launch_bounds__(NTHR) regloss_reduce(
    const float* __restrict__ loc,
    const float* __restrict__ cord,
    const float* __restrict__ tw)
{
    const float4* __restrict__ loc0 = reinterpret_cast<const float4*>(loc);
    const float4* __restrict__ loc1 = reinterpret_cast<const float4*>(loc + NTOT);

    float acc = 0.0f;
    const int stride = gridDim.x * blockDim.x;
    for (int i = blockIdx.x * blockDim.x + threadIdx.x; i < N4; i += stride) {
        const int n  = i * 4;
        const int m  = n / YX;            // = b*J + j (same flat index for tw AND cord)
        const int p  = n - m * YX;
        const int y  = p / XX;
        const int x0 = p - y * XX;

        const float w  = __ldg(tw + m);
        const float cx = __ldg(cord + m);            // cord[0] flat index == m
        const float cy = __ldg(cord + JJ * BB + m);  // cord[1]

        const float4 lx = __ldg(loc0 + i);
        const float4 ly = __ldg(loc1 + i);

        // int32-truncated ground-truth shifts (toward zero, matches astype(int32))
        const float gy  = truncf((float)y - cy);
        const float gx0 = truncf((float)(x0 + 0) - cx);
        const float gx1 = truncf((float)(x0 + 1) - cx);
        const float gx2 = truncf((float)(x0 + 2) - cx);
        const float gx3 = truncf((float)(x0 + 3) - cx);

        float d;
        d = (lx.x - gx0) * w; acc = fmaf(d, d, acc);
        d = (lx.y - gx1) * w; acc = fmaf(d, d, acc);
        d = (lx.z - gx2) * w; acc = fmaf(d, d, acc);
        d = (lx.w - gx3) * w; acc = fmaf(d, d, acc);
        d = (ly.x - gy)  * w; acc = fmaf(d, d, acc);
        d = (ly.y - gy)  * w; acc = fmaf(d, d, acc);
        d = (ly.z - gy)  * w; acc = fmaf(d, d, acc);
        d = (ly.w - gy)  * w; acc = fmaf(d, d, acc);
    }

    // Block tree reduction in shared memory (deterministic)
    __shared__ float sm[NTHR];
    sm[threadIdx.x] = acc;
    __syncthreads();
    #pragma unroll
    for (int s = NTHR / 2; s >= 32; s >>= 1) {
        if (threadIdx.x < s) sm[threadIdx.x] += sm[threadIdx.x + s];
        __syncthreads();
    }
    if (threadIdx.x < 32) {
        float v = sm[threadIdx.x];
        #pragma unroll
        for (int off = 16; off > 0; off >>= 1)
            v += __shfl_down_sync(0xFFFFFFFFu, v, off);
        if (threadIdx.x == 0)
            g_partials[blockIdx.x] = (double)v;
    }
    // NOTE: no fence, no atomic, no trigger. Implicit PDL trigger fires at
    // kernel completion, which carries full memory visibility to the
    // dependent grid's cudaGridDependencySynchronize().
}

// ── Secondary: launched with ProgrammaticStreamSerialization so its launch
//    ramp overlaps the primary's drain. Gated by gridDependencySynchronize. ──
__global__ void __launch_bounds__(NTHR) regloss_finalize(float* __restrict__ out)
{
    cudaGridDependencySynchronize();   // wait: primary complete + mem visible

    __shared__ double sm[NTHR];
    double s = 0.0;
    #pragma unroll
    for (int i = threadIdx.x; i < NBLK; i += NTHR)
        s += g_partials[i];
    sm[threadIdx.x] = s;
    __syncthreads();
    #pragma unroll
    for (int st = NTHR / 2; st > 0; st >>= 1) {
        if (threadIdx.x < st) sm[threadIdx.x] += sm[threadIdx.x + st];
        __syncthreads();
    }
    if (threadIdx.x == 0) {
        // loss = 0.5 * Sigma / (B*YX) / J
        const double scale = 0.5 / (double)NTOT;
        out[0] = (float)(sm[0] * scale);
    }
}

extern "C" void kernel_launch(void* const* d_in, const int* in_sizes, int n_in,
                              void* d_out, int out_size)
{
    const float* loc  = (const float*)d_in[0];   // (2, B, J, Y, X) fp32
    const float* cord = (const float*)d_in[1];   // (2, J, B) fp32
    const float* tw   = (const float*)d_in[2];   // (B, J, 1) fp32
    float* out = (float*)d_out;

    regloss_reduce<<<NBLK, NTHR>>>(loc, cord, tw);

    // PDL launch of the finalize kernel on the same (legacy) stream.
    cudaLaunchConfig_t cfg = {};
    cfg.gridDim          = dim3(1, 1, 1);
    cfg.blockDim         = dim3(NTHR, 1, 1);
    cfg.dynamicSmemBytes = 0;
    cfg.stream           = 0;              // legacy default stream (same as <<<>>>)
    cudaLaunchAttribute attr[1];
    attr[0].id = cudaLaunchAttributeProgrammaticStreamSerialization;
    attr[0].val.programmaticStreamSerializationAllowed = 1;
    cfg.attrs    = attr;
    cfg.numAttrs = 1;
    cudaLaunchKernelEx(&cfg, regloss_finalize, out);
}

// round 10
// speedup vs baseline: 1.1470x; 1.1099x over previous
#include <cuda_runtime.h>

// Problem constants
#define BB 128
#define JJ 17
#define YY 96
#define XX 72
#define YX (YY * XX)                 // 6912
#define NTOT (BB * JJ * YX)          // 15,040,512 elements per plane
#define N4 (NTOT / 4)                // 3,760,128 float4 chunks per plane

#define NBLK 1184                    // 148 SMs * 8 blocks (2048 thr/SM, one wave)
#define NTHR 256

// ── Prologue: trivially cheap node, zeroes the output accumulator ──
__global__ void regloss_zero(float* __restrict__ out)
{
    if (threadIdx.x == 0) out[0] = 0.0f;
}

// ── Main: hot loop byte-identical to the proven 18.6us R4 streaming kernel.
//    Epilogue is ONE float atomicAdd per block — no fence, no flags, no tail. ──
__global__ void __launch_bounds__(NTHR) regloss_reduce(
    const float* __restrict__ loc,
    const float* __restrict__ cord,
    const float* __restrict__ tw,
    float* __restrict__ out)
{
    const float4* __restrict__ loc0 = reinterpret_cast<const float4*>(loc);
    const float4* __restrict__ loc1 = reinterpret_cast<const float4*>(loc + NTOT);

    float acc = 0.0f;
    const int stride = gridDim.x * blockDim.x;
    for (int i = blockIdx.x * blockDim.x + threadIdx.x; i < N4; i += stride) {
        const int n  = i * 4;
        const int m  = n / YX;            // = b*J + j (same flat index for tw AND cord)
        const int p  = n - m * YX;
        const int y  = p / XX;
        const int x0 = p - y * XX;

        const float w  = __ldg(tw + m);
        const float cx = __ldg(cord + m);            // cord[0] flat index == m
        const float cy = __ldg(cord + JJ * BB + m);  // cord[1]

        const float4 lx = __ldg(loc0 + i);
        const float4 ly = __ldg(loc1 + i);

        // int32-truncated ground-truth shifts (toward zero, matches astype(int32))
        const float gy  = truncf((float)y - cy);
        const float gx0 = truncf((float)(x0 + 0) - cx);
        const float gx1 = truncf((float)(x0 + 1) - cx);
        const float gx2 = truncf((float)(x0 + 2) - cx);
        const float gx3 = truncf((float)(x0 + 3) - cx);

        float d;
        d = (lx.x - gx0) * w; acc = fmaf(d, d, acc);
        d = (lx.y - gx1) * w; acc = fmaf(d, d, acc);
        d = (lx.z - gx2) * w; acc = fmaf(d, d, acc);
        d = (lx.w - gx3) * w; acc = fmaf(d, d, acc);
        d = (ly.x - gy)  * w; acc = fmaf(d, d, acc);
        d = (ly.y - gy)  * w; acc = fmaf(d, d, acc);
        d = (ly.z - gy)  * w; acc = fmaf(d, d, acc);
        d = (ly.w - gy)  * w; acc = fmaf(d, d, acc);
    }

    // Block tree reduction in shared memory (deterministic within block)
    __shared__ float sm[NTHR];
    sm[threadIdx.x] = acc;
    __syncthreads();
    #pragma unroll
    for (int s = NTHR / 2; s >= 32; s >>= 1) {
        if (threadIdx.x < s) sm[threadIdx.x] += sm[threadIdx.x + s];
        __syncthreads();
    }
    if (threadIdx.x < 32) {
        float v = sm[threadIdx.x];
        #pragma unroll
        for (int off = 16; off > 0; off >>= 1)
            v += __shfl_down_sync(0xFFFFFFFFu, v, off);
        if (threadIdx.x == 0) {
            // loss contribution: 0.5 * partial / (B*YX*J). Scale in double,
            // add in float. 1184 same-address atomics ~= 1k cycles total.
            const double scale = 0.5 / (double)NTOT;
            atomicAdd(out, (float)((double)v * scale));
        }
    }
}

extern "C" void kernel_launch(void* const* d_in, const int* in_sizes, int n_in,
                              void* d_out, int out_size)
{
    const float* loc  = (const float*)d_in[0];   // (2, B, J, Y, X) fp32
    const float* cord = (const float*)d_in[1];   // (2, J, B) fp32
    const float* tw   = (const float*)d_in[2];   // (B, J, 1) fp32
    float* out = (float*)d_out;

    regloss_zero<<<1, 32>>>(out);
    regloss_reduce<<<NBLK, NTHR>>>(loc, cord, tw, out);
}

// round 11
// speedup vs baseline: 1.1613x; 1.0125x over previous
#include <cuda_runtime.h>

// Problem constants
#define BB 128
#define JJ 17
#define YY 96
#define XX 72
#define YX (YY * XX)                 // 6912
#define NTOT (BB * JJ * YX)          // 15,040,512 elements per plane
#define N4 (NTOT / 4)                // 3,760,128 float4 chunks per plane

#define NBLK 592                     // 148 SMs * 4 blocks (1024 thr/SM -> 64 regs/thr)
#define NTHR 256
#define CPT 4                        // chunks per thread per tile iteration
#define TILE (NBLK * NTHR * CPT)     // 606,208 chunks per tile
#define FULL_ITERS 6                 // 6*TILE = 3,637,248 <= N4
#define TAIL_BASE (FULL_ITERS * TILE)

static __device__ float        g_acc   = 0.0f;  // self-resets via atomicExch
static __device__ unsigned int g_count = 0;     // self-resets via atom.inc wrap

// Per-chunk math: 4 x-elements + 4 y-elements of squared weighted error.
__device__ __forceinline__ float chunk_term(
    int i, float4 lx, float4 ly,
    const float* __restrict__ cord, const float* __restrict__ tw)
{
    const int n  = i * 4;
    const int m  = n / YX;            // = b*J + j (same flat index for tw AND cord)
    const int p  = n - m * YX;
    const int y  = p / XX;
    const int x0 = p - y * XX;

    const float w  = __ldg(tw + m);
    const float cx = __ldg(cord + m);            // cord[0] flat index == m
    const float cy = __ldg(cord + JJ * BB + m);  // cord[1]

    // int32-truncated ground-truth shifts (toward zero, matches astype(int32))
    const float gy  = truncf((float)y - cy);
    const float gx0 = truncf((float)(x0 + 0) - cx);
    const float gx1 = truncf((float)(x0 + 1) - cx);
    const float gx2 = truncf((float)(x0 + 2) - cx);
    const float gx3 = truncf((float)(x0 + 3) - cx);

    float t = 0.0f, d;
    d = (lx.x - gx0) * w; t = fmaf(d, d, t);
    d = (lx.y - gx1) * w; t = fmaf(d, d, t);
    d = (lx.z - gx2) * w; t = fmaf(d, d, t);
    d = (lx.w - gx3) * w; t = fmaf(d, d, t);
    d = (ly.x - gy)  * w; t = fmaf(d, d, t);
    d = (ly.y - gy)  * w; t = fmaf(d, d, t);
    d = (ly.z - gy)  * w; t = fmaf(d, d, t);
    d = (ly.w - gy)  * w; t = fmaf(d, d, t);
    return t;
}

__global__ void __launch_bounds__(NTHR, 4) regloss_reduce(
    const float* __restrict__ loc,
    const float* __restrict__ cord,
    const float* __restrict__ tw,
    float* __restrict__ out)
{
    const float4* __restrict__ loc0 = reinterpret_cast<const float4*>(loc);
    const float4* __restrict__ loc1 = reinterpret_cast<const float4*>(loc + NTOT);

    const int base = blockIdx.x * (CPT * NTHR) + threadIdx.x;

    float acc = 0.0f;
    #pragma unroll 1
    for (int it = 0; it < FULL_ITERS; ++it) {
        const int i0 = it * TILE + base;
        const int i1 = i0 + NTHR;
        const int i2 = i0 + 2 * NTHR;
        const int i3 = i0 + 3 * NTHR;
        // Front-batch all 8 x 128-bit loads for deep MLP
        const float4 a0 = __ldg(loc0 + i0);
        const float4 a1 = __ldg(loc0 + i1);
        const float4 a2 = __ldg(loc0 + i2);
        const float4 a3 = __ldg(loc0 + i3);
        const float4 b0 = __ldg(loc1 + i0);
        const float4 b1 = __ldg(loc1 + i1);
        const float4 b2 = __ldg(loc1 + i2);
        const float4 b3 = __ldg(loc1 + i3);
        acc += chunk_term(i0, a0, b0, cord, tw);
        acc += chunk_term(i1, a1, b1, cord, tw);
        acc += chunk_term(i2, a2, b2, cord, tw);
        acc += chunk_term(i3, a3, b3, cord, tw);
    }
    // Tail: 122,880 remaining chunks, <=1 per thread
    {
        const int i = TAIL_BASE + blockIdx.x * NTHR + threadIdx.x;
        if (i < N4) {
            const float4 a = __ldg(loc0 + i);
            const float4 b = __ldg(loc1 + i);
            acc += chunk_term(i, a, b, cord, tw);
        }
    }

    // ── Block tree reduction (deterministic within block) ──
    __shared__ float sm[NTHR];
    sm[threadIdx.x] = acc;
    __syncthreads();
    #pragma unroll
    for (int s = NTHR / 2; s >= 32; s >>= 1) {
        if (threadIdx.x < s) sm[threadIdx.x] += sm[threadIdx.x + s];
        __syncthreads();
    }
    if (threadIdx.x < 32) {
        float v = sm[threadIdx.x];
        #pragma unroll
        for (int off = 16; off > 0; off >>= 1)
            v += __shfl_down_sync(0xFFFFFFFFu, v, off);
        if (threadIdx.x == 0) {
            // Scaled block partial into global accumulator.
            const double scale = 0.5 / (double)NTOT;
            const float contrib = (float)((double)v * scale);

            float* accp = &g_acc;
            unsigned int* cntp = &g_count;

            // release-add: no fence, no L1 flush
            asm volatile("red.release.gpu.add.f32 [%0], %1;"
                         :: "l"(accp), "f"(contrib) : "memory");
            // release-inc orders this thread's add before the count bump;
            // wraps NBLK-1 -> 0 so it self-resets for the next graph replay.
            unsigned int old;
            asm volatile("atom.release.gpu.inc.u32 %0, [%1], %2;"
                         : "=r"(old) : "l"(cntp), "r"(NBLK - 1u) : "memory");
            if (old == NBLK - 1u) {
                // acquire-exchange: returns the complete sum (all adds are
                // ordered before their incs; our acquire syncs with them)
                // and resets the accumulator to 0 for the next replay.
                unsigned int bits;
                asm volatile("atom.acquire.gpu.exch.b32 %0, [%1], %2;"
                             : "=r"(bits) : "l"(accp), "r"(0u) : "memory");
                out[0] = __uint_as_float(bits);
            }
        }
    }
}

extern "C" void kernel_launch(void* const* d_in, const int* in_sizes, int n_in,
                              void* d_out, int out_size)
{
    const float* loc  = (const float*)d_in[0];   // (2, B, J, Y, X) fp32
    const float* cord = (const float*)d_in[1];   // (2, J, B) fp32
    const float* tw   = (const float*)d_in[2];   // (B, J, 1) fp32
    float* out = (float*)d_out;

    regloss_reduce<<<NBLK, NTHR>>>(loc, cord, tw, out);
}